// round 12
// baseline (speedup 1.0000x reference)
#include <cuda_runtime.h>
#include <cuda_fp16.h>
#include <cuda_bf16.h>
#include <math.h>

#define V_  5
#define C_  32
#define H_  384
#define W_  384
#define D_  4
#define G_  8
#define HW_ (H_ * W_)          // 147456
#define TPB_PIX 256            // pixels per transpose block
#define NPT (HW_ / TPB_PIX)    // transpose blocks per view: 576

// Reference view (view 0) transposed, fp32: (H*W, C)
__device__ float  g_refT[(size_t)HW_ * C_];        // 18.9 MB
// Source views (1..4) transposed, fp16: (4, H*W, C) -- 37.7 MB, L2-resident
__device__ __half g_srcT[(size_t)4 * HW_ * C_];
// Folded projection per source view: uvd = M_s * (gx,gy,1) * dep + c_s
__device__ float g_M[4][9];
__device__ float g_c[4][3];

__device__ __forceinline__ void invert3f(const float* m, float* inv) {
    float a = m[0], b = m[1], c = m[2];
    float d = m[3], e = m[4], f = m[5];
    float g = m[6], h = m[7], i = m[8];
    float A  =  (e*i - f*h);
    float Bc = -(d*i - f*g);
    float Cc =  (d*h - e*g);
    float det = a*A + b*Bc + c*Cc;
    float id = 1.0f / det;
    inv[0] = A * id;
    inv[1] = -(b*i - c*h) * id;
    inv[2] =  (b*f - c*e) * id;
    inv[3] = Bc * id;
    inv[4] =  (a*i - c*g) * id;
    inv[5] = -(a*f - c*d) * id;
    inv[6] = Cc * id;
    inv[7] = -(a*h - b*g) * id;
    inv[8] =  (a*e - b*d) * id;
}

__device__ __forceinline__ void mat3mulf(const float* A, const float* B, float* Cm) {
    #pragma unroll
    for (int i = 0; i < 3; i++)
        #pragma unroll
        for (int j = 0; j < 3; j++)
            Cm[i*3+j] = A[i*3+0]*B[0*3+j] + A[i*3+1]*B[1*3+j] + A[i*3+2]*B[2*3+j];
}

// Fused: blocks [0, NPT*V) transpose CHW->HWC (256 pixels / 8 tiles per block);
// view 0 -> fp32 ref, views 1..4 -> fp16 src. Block NPT*V folds cameras (fp32).
__global__ void __launch_bounds__(1024)
transpose_setup_kernel(const float* __restrict__ f,
                       const float* __restrict__ K,
                       const float* __restrict__ E) {
    if (blockIdx.x == NPT * V_) {
        const int s = threadIdx.x + threadIdx.y * 32;
        if (s < 4) {
            float K0[9], Kinv[9], R0[9], Rinv[9], t0[3];
            #pragma unroll
            for (int i = 0; i < 9; i++) K0[i] = K[i];
            invert3f(K0, Kinv);
            #pragma unroll
            for (int i = 0; i < 3; i++) {
                #pragma unroll
                for (int j = 0; j < 3; j++) R0[i*3+j] = E[i*4+j];
                t0[i] = E[i*4+3];
            }
            invert3f(R0, Rinv);

            float Ks[9], Rs[9], ts[3];
            #pragma unroll
            for (int i = 0; i < 9; i++) Ks[i] = K[(s+1)*9 + i];
            #pragma unroll
            for (int i = 0; i < 3; i++) {
                #pragma unroll
                for (int j = 0; j < 3; j++) Rs[i*3+j] = E[(s+1)*12 + i*4 + j];
                ts[i] = E[(s+1)*12 + i*4 + 3];
            }
            float A[9], Bm[9], M[9];
            mat3mulf(Rs, Rinv, A);
            mat3mulf(Ks, A, Bm);
            mat3mulf(Bm, Kinv, M);
            #pragma unroll
            for (int i = 0; i < 3; i++) {
                float kt = Ks[i*3+0]*ts[0] + Ks[i*3+1]*ts[1] + Ks[i*3+2]*ts[2];
                float bt = Bm[i*3+0]*t0[0] + Bm[i*3+1]*t0[1] + Bm[i*3+2]*t0[2];
                g_c[s][i] = kt - bt;
            }
            #pragma unroll
            for (int i = 0; i < 9; i++) g_M[s][i] = M[i];
        }
        return;
    }
    __shared__ float sbuf[8][32][33];
    const int v  = blockIdx.x / NPT;
    const int p0 = (blockIdx.x - v * NPT) * TPB_PIX;
    const int tx = threadIdx.x, ty = threadIdx.y;
    #pragma unroll
    for (int t = 0; t < 8; t++)
        sbuf[t][ty][tx] = f[((size_t)v * C_ + ty) * HW_ + p0 + t * 32 + tx];
    __syncthreads();
    if (v == 0) {
        #pragma unroll
        for (int t = 0; t < 8; t++)
            g_refT[(size_t)(p0 + t * 32 + ty) * C_ + tx] = sbuf[t][tx][ty];
    } else {
        #pragma unroll
        for (int t = 0; t < 8; t++)
            g_srcT[((size_t)(v - 1) * HW_ + (p0 + t * 32 + ty)) * C_ + tx] =
                __float2half(sbuf[t][tx][ty]);
    }
}

// Streaming store for output.
__device__ __forceinline__ void stg_cs(float* p, float v) {
    asm volatile("st.global.cs.f32 [%0], %1;" :: "l"(p), "f"(v) : "memory");
}

// Main kernel: 256 threads = 32 pixels x 8 group-lanes. 4 blocks/SM (64 regs),
// fp16 src gathers batched one view (16 x uint2 = 32 data regs) at a time.
__global__ void __launch_bounds__(256, 4)
gbinet_main_kernel(const float* __restrict__ depths,
                   const float* __restrict__ w0, const float* __restrict__ b0,
                   const float* __restrict__ w1, const float* __restrict__ b1,
                   const float* __restrict__ w2, const float* __restrict__ b2,
                   float* __restrict__ out) {
    __shared__ float sw0[16*8], sb0[16], sw1[8*16], sb1[8], sw2[8], sb2v[1];
    __shared__ float sM[4][9], sc[4][3];
    __shared__ float ssim[4 * 4 * 32 * 9];   // [s][d][pixL][g(pad 9)] = 18 KB
    __shared__ float ssig[4 * 4 * 32];       // [s][d][pixL]
    __shared__ float svw[4 * 32];            // [s][pixL]

    const int tid  = threadIdx.x;
    const int pixL = tid >> 3;
    const int g    = tid & 7;

    if (tid < 128) sw0[tid] = w0[tid];
    else           sw1[tid - 128] = w1[tid - 128];
    if (tid < 16) sb0[tid] = b0[tid];
    if (tid >= 16 && tid < 24) sb1[tid - 16] = b1[tid - 16];
    if (tid >= 24 && tid < 32) sw2[tid - 24] = w2[tid - 24];
    if (tid == 32) sb2v[0] = b2[0];
    if (tid >= 64 && tid < 64 + 36) {
        int i = tid - 64; sM[i / 9][i % 9] = g_M[i / 9][i % 9];
    }
    if (tid >= 100 && tid < 112) {
        int i = tid - 100; sc[i / 3][i % 3] = g_c[i / 3][i % 3];
    }

    const int pix = blockIdx.x * 32 + pixL;
    const int y = pix / W_;
    const int x = pix - y * W_;
    const float gx = (float)x + 0.5f;
    const float gy = (float)y + 0.5f;

    float dep[D_];
    #pragma unroll
    for (int d = 0; d < D_; d++) dep[d] = depths[d * HW_ + pix];

    const float4 ref = ((const float4*)g_refT)[(size_t)pix * 8 + g];
    const uint2* __restrict__ src2 = (const uint2*)g_srcT;

    __syncthreads();   // weights + M/c visible

    // ---- gather phase: one view (16 x uint2 loads) batched per pass ----
    #pragma unroll 1
    for (int s = 0; s < 4; s++) {
        const float mx = sM[s][0]*gx + sM[s][1]*gy + sM[s][2];
        const float my = sM[s][3]*gx + sM[s][4]*gy + sM[s][5];
        const float mz = sM[s][6]*gx + sM[s][7]*gy + sM[s][8];
        const size_t vbase = (size_t)s * HW_;
        #pragma unroll
        for (int d = 0; d < D_; d++) {
            const float uh = fmaf(mx, dep[d], sc[s][0]);
            const float vh = fmaf(my, dep[d], sc[s][1]);
            const float zh = fmaf(mz, dep[d], sc[s][2]);
            const float rz = 1.0f / (zh + 1e-9f);
            const float px = uh * rz;
            const float py = vh * rz;

            const float x0f = floorf(px);
            const float y0f = floorf(py);
            const float wx1 = px - x0f, wx0v = 1.0f - wx1;
            const float wy1 = py - y0f, wy0v = 1.0f - wy1;

            float acc = 0.0f;
            #pragma unroll
            for (int corner = 0; corner < 4; corner++) {
                const float xf = x0f + (float)(corner & 1);
                const float yf = y0f + (float)(corner >> 1);
                const float w = ((corner & 1) ? wx1 : wx0v) *
                                ((corner >> 1) ? wy1 : wy0v);
                if (xf >= 0.0f && xf <= (float)(W_ - 1) &&
                    yf >= 0.0f && yf <= (float)(H_ - 1)) {
                    const int xi = (int)xf;
                    const int yi = (int)yf;
                    const uint2 q = __ldg(src2 + (vbase + (size_t)yi * W_ + xi) * 8 + g);
                    const __half2 h01 = *reinterpret_cast<const __half2*>(&q.x);
                    const __half2 h23 = *reinterpret_cast<const __half2*>(&q.y);
                    const float2 f01 = __half22float2(h01);
                    const float2 f23 = __half22float2(h23);
                    const float dot = f01.x*ref.x + f01.y*ref.y +
                                      f23.x*ref.z + f23.y*ref.w;
                    acc = fmaf(w, dot, acc);
                }
            }
            ssim[((s * 4 + d) * 32 + pixL) * 9 + g] = 0.25f * acc;
        }
    }
    __syncthreads();

    // ---- MLP phase: 512 (s,d,pix) items over 256 threads, 2 each ----
    #pragma unroll
    for (int it = 0; it < 2; it++) {
        const int i  = tid + it * 256;
        const int pp = i & 31;
        const int d  = (i >> 5) & 3;
        const int s  = i >> 7;
        const int base = ((s * 4 + d) * 32 + pp) * 9;
        float sv[8];
        #pragma unroll
        for (int k = 0; k < 8; k++) sv[k] = ssim[base + k];

        float x0v[16];
        #pragma unroll
        for (int o = 0; o < 16; o++) {
            float t = sb0[o];
            #pragma unroll
            for (int k = 0; k < 8; k++) t = fmaf(sw0[o*8 + k], sv[k], t);
            x0v[o] = fmaxf(t, 0.0f);
        }
        float x1v[8];
        #pragma unroll
        for (int j = 0; j < 8; j++) {
            float t = sb1[j];
            #pragma unroll
            for (int o = 0; o < 16; o++) t = fmaf(sw1[j*16 + o], x0v[o], t);
            x1v[j] = fmaxf(t, 0.0f);
        }
        float yv = sb2v[0];
        #pragma unroll
        for (int j = 0; j < 8; j++) yv = fmaf(sw2[j], x1v[j], yv);
        ssig[(s * 4 + d) * 32 + pp] = 1.0f / (1.0f + expf(-yv));
    }
    __syncthreads();

    // ---- depth max: vw[s][pix] = max_d sigmoid ----
    if (tid < 128) {
        const int s  = tid >> 5;
        const int pp = tid & 31;
        float m = ssig[(s * 4 + 0) * 32 + pp];
        #pragma unroll
        for (int d = 1; d < 4; d++) m = fmaxf(m, ssig[(s * 4 + d) * 32 + pp]);
        svw[s * 32 + pp] = m;
    }
    __syncthreads();

    // ---- accumulate + output (streaming stores) ----
    float simsum[D_] = {0.0f, 0.0f, 0.0f, 0.0f};
    float wsum = 0.0f;
    #pragma unroll
    for (int s = 0; s < 4; s++) {
        const float vw = svw[s * 32 + pixL];
        wsum += vw;
        #pragma unroll
        for (int d = 0; d < D_; d++)
            simsum[d] = fmaf(ssim[((s * 4 + d) * 32 + pixL) * 9 + g], vw, simsum[d]);
    }
    const float invw = 1.0f / wsum;
    #pragma unroll
    for (int d = 0; d < D_; d++)
        stg_cs(out + (size_t)(g * D_ + d) * HW_ + pix, simsum[d] * invw);
}

extern "C" void kernel_launch(void* const* d_in, const int* in_sizes, int n_in,
                              void* d_out, int out_size) {
    const float* features = (const float*)d_in[0];  // (5,1,32,384,384)
    const float* depths   = (const float*)d_in[1];  // (1,4,384,384)
    const float* Kall     = (const float*)d_in[2];  // (1,5,3,3)
    const float* Eall     = (const float*)d_in[3];  // (1,5,3,4)
    const float* w0 = (const float*)d_in[4];
    const float* b0 = (const float*)d_in[5];
    const float* w1 = (const float*)d_in[6];
    const float* b1 = (const float*)d_in[7];
    const float* w2 = (const float*)d_in[8];
    const float* b2 = (const float*)d_in[9];
    float* out = (float*)d_out;
    (void)in_sizes; (void)n_in; (void)out_size;

    dim3 tb(32, 32);
    transpose_setup_kernel<<<NPT * V_ + 1, tb>>>(features, Kall, Eall);

    gbinet_main_kernel<<<HW_ / 32, 256>>>(depths, w0, b0, w1, b1, w2, b2, out);
}

// round 13
// speedup vs baseline: 1.5588x; 1.5588x over previous
#include <cuda_runtime.h>
#include <cuda_bf16.h>
#include <math.h>

#define V_  5
#define C_  32
#define H_  384
#define W_  384
#define D_  4
#define G_  8
#define HW_ (H_ * W_)          // 147456
#define TPB_PIX 256            // pixels per transpose block
#define NPT (HW_ / TPB_PIX)    // transpose blocks per view: 576

// Transposed features (V, H*W, C): per-pixel channels contiguous, fp32.
__device__ float g_featT[(size_t)V_ * HW_ * C_];   // ~94.4 MB
// Folded projection per source view: uvd = M_s * (gx,gy,1) * dep + c_s
__device__ float g_M[4][9];
__device__ float g_c[4][3];

__device__ __forceinline__ void invert3f(const float* m, float* inv) {
    float a = m[0], b = m[1], c = m[2];
    float d = m[3], e = m[4], f = m[5];
    float g = m[6], h = m[7], i = m[8];
    float A  =  (e*i - f*h);
    float Bc = -(d*i - f*g);
    float Cc =  (d*h - e*g);
    float det = a*A + b*Bc + c*Cc;
    float id = 1.0f / det;
    inv[0] = A * id;
    inv[1] = -(b*i - c*h) * id;
    inv[2] =  (b*f - c*e) * id;
    inv[3] = Bc * id;
    inv[4] =  (a*i - c*g) * id;
    inv[5] = -(a*f - c*d) * id;
    inv[6] = Cc * id;
    inv[7] = -(a*h - b*g) * id;
    inv[8] =  (a*e - b*d) * id;
}

__device__ __forceinline__ void mat3mulf(const float* A, const float* B, float* Cm) {
    #pragma unroll
    for (int i = 0; i < 3; i++)
        #pragma unroll
        for (int j = 0; j < 3; j++)
            Cm[i*3+j] = A[i*3+0]*B[0*3+j] + A[i*3+1]*B[1*3+j] + A[i*3+2]*B[2*3+j];
}

// Fused: blocks [0, NPT*V) transpose CHW->HWC (256 pixels / 8 tiles per block);
// block NPT*V folds cameras (fp32, 4 threads).
__global__ void __launch_bounds__(1024)
transpose_setup_kernel(const float* __restrict__ f,
                       const float* __restrict__ K,
                       const float* __restrict__ E) {
    if (blockIdx.x == NPT * V_) {
        const int s = threadIdx.x + threadIdx.y * 32;
        if (s < 4) {
            float K0[9], Kinv[9], R0[9], Rinv[9], t0[3];
            #pragma unroll
            for (int i = 0; i < 9; i++) K0[i] = K[i];
            invert3f(K0, Kinv);
            #pragma unroll
            for (int i = 0; i < 3; i++) {
                #pragma unroll
                for (int j = 0; j < 3; j++) R0[i*3+j] = E[i*4+j];
                t0[i] = E[i*4+3];
            }
            invert3f(R0, Rinv);

            float Ks[9], Rs[9], ts[3];
            #pragma unroll
            for (int i = 0; i < 9; i++) Ks[i] = K[(s+1)*9 + i];
            #pragma unroll
            for (int i = 0; i < 3; i++) {
                #pragma unroll
                for (int j = 0; j < 3; j++) Rs[i*3+j] = E[(s+1)*12 + i*4 + j];
                ts[i] = E[(s+1)*12 + i*4 + 3];
            }
            float A[9], Bm[9], M[9];
            mat3mulf(Rs, Rinv, A);
            mat3mulf(Ks, A, Bm);
            mat3mulf(Bm, Kinv, M);
            #pragma unroll
            for (int i = 0; i < 3; i++) {
                float kt = Ks[i*3+0]*ts[0] + Ks[i*3+1]*ts[1] + Ks[i*3+2]*ts[2];
                float bt = Bm[i*3+0]*t0[0] + Bm[i*3+1]*t0[1] + Bm[i*3+2]*t0[2];
                g_c[s][i] = kt - bt;
            }
            #pragma unroll
            for (int i = 0; i < 9; i++) g_M[s][i] = M[i];
        }
        return;
    }
    __shared__ float sbuf[8][32][33];
    const int v  = blockIdx.x / NPT;
    const int p0 = (blockIdx.x - v * NPT) * TPB_PIX;
    const int tx = threadIdx.x, ty = threadIdx.y;
    #pragma unroll
    for (int t = 0; t < 8; t++)
        sbuf[t][ty][tx] = f[((size_t)v * C_ + ty) * HW_ + p0 + t * 32 + tx];
    __syncthreads();
    #pragma unroll
    for (int t = 0; t < 8; t++)
        g_featT[(size_t)v * HW_ * C_ + (size_t)(p0 + t * 32 + ty) * C_ + tx] =
            sbuf[t][tx][ty];
}

// Streaming store for output.
__device__ __forceinline__ void stg_cs(float* p, float v) {
    asm volatile("st.global.cs.f32 [%0], %1;" :: "l"(p), "f"(v) : "memory");
}

// Main kernel: 256 threads = 32 pixels x 8 group-lanes. 2 blocks/SM (128 regs),
// gathers batched 2 views (32 loads) at a time, 32-bit indexing + fast rcp.
__global__ void __launch_bounds__(256, 2)
gbinet_main_kernel(const float* __restrict__ depths,
                   const float* __restrict__ w0, const float* __restrict__ b0,
                   const float* __restrict__ w1, const float* __restrict__ b1,
                   const float* __restrict__ w2, const float* __restrict__ b2,
                   float* __restrict__ out) {
    __shared__ float sw0[16*8], sb0[16], sw1[8*16], sb1[8], sw2[8], sb2v[1];
    __shared__ float sM[4][9], sc[4][3];
    __shared__ float ssim[4 * 4 * 32 * 9];   // [s][d][pixL][g(pad 9)] = 18 KB
    __shared__ float ssig[4 * 4 * 32];       // [s][d][pixL]
    __shared__ float svw[4 * 32];            // [s][pixL]

    const int tid  = threadIdx.x;
    const int pixL = tid >> 3;
    const int g    = tid & 7;

    if (tid < 128) sw0[tid] = w0[tid];
    else           sw1[tid - 128] = w1[tid - 128];
    if (tid < 16) sb0[tid] = b0[tid];
    if (tid >= 16 && tid < 24) sb1[tid - 16] = b1[tid - 16];
    if (tid >= 24 && tid < 32) sw2[tid - 24] = w2[tid - 24];
    if (tid == 32) sb2v[0] = b2[0];
    if (tid >= 64 && tid < 64 + 36) {
        int i = tid - 64; sM[i / 9][i % 9] = g_M[i / 9][i % 9];
    }
    if (tid >= 100 && tid < 112) {
        int i = tid - 100; sc[i / 3][i % 3] = g_c[i / 3][i % 3];
    }

    const int pix = blockIdx.x * 32 + pixL;
    const int y = pix / W_;
    const int x = pix - y * W_;
    const float gx = (float)x + 0.5f;
    const float gy = (float)y + 0.5f;

    float dep[D_];
    #pragma unroll
    for (int d = 0; d < D_; d++) dep[d] = depths[d * HW_ + pix];

    const float4* __restrict__ fT4 = (const float4*)g_featT;
    const float4 ref = fT4[pix * 8 + g];

    __syncthreads();   // weights + M/c visible

    // ---- gather phase: 2 views (32 loads) batched per pass ----
    #pragma unroll 2
    for (int s = 0; s < 4; s++) {
        const float mx = sM[s][0]*gx + sM[s][1]*gy + sM[s][2];
        const float my = sM[s][3]*gx + sM[s][4]*gy + sM[s][5];
        const float mz = sM[s][6]*gx + sM[s][7]*gy + sM[s][8];
        const int vbase = (s + 1) * HW_;   // 32-bit: max 5*147456
        #pragma unroll
        for (int d = 0; d < D_; d++) {
            const float uh = fmaf(mx, dep[d], sc[s][0]);
            const float vh = fmaf(my, dep[d], sc[s][1]);
            const float zh = fmaf(mz, dep[d], sc[s][2]);
            const float rz = __fdividef(1.0f, zh + 1e-9f);   // MUFU rcp
            const float px = uh * rz;
            const float py = vh * rz;

            const float x0f = floorf(px);
            const float y0f = floorf(py);
            const float wx1 = px - x0f, wx0v = 1.0f - wx1;
            const float wy1 = py - y0f, wy0v = 1.0f - wy1;

            float acc = 0.0f;
            #pragma unroll
            for (int corner = 0; corner < 4; corner++) {
                const float xf = x0f + (float)(corner & 1);
                const float yf = y0f + (float)(corner >> 1);
                const float w = ((corner & 1) ? wx1 : wx0v) *
                                ((corner >> 1) ? wy1 : wy0v);
                if (xf >= 0.0f && xf <= (float)(W_ - 1) &&
                    yf >= 0.0f && yf <= (float)(H_ - 1)) {
                    const int xi = (int)xf;
                    const int yi = (int)yf;
                    const int idx = (vbase + yi * W_ + xi) * 8 + g;  // < 2^31
                    const float4 f = __ldg(fT4 + idx);
                    const float dot = f.x*ref.x + f.y*ref.y + f.z*ref.z + f.w*ref.w;
                    acc = fmaf(w, dot, acc);
                }
            }
            ssim[((s * 4 + d) * 32 + pixL) * 9 + g] = 0.25f * acc;
        }
    }
    __syncthreads();

    // ---- MLP phase: 512 (s,d,pix) items over 256 threads, 2 each ----
    #pragma unroll
    for (int it = 0; it < 2; it++) {
        const int i  = tid + it * 256;
        const int pp = i & 31;
        const int d  = (i >> 5) & 3;
        const int s  = i >> 7;
        const int base = ((s * 4 + d) * 32 + pp) * 9;
        float sv[8];
        #pragma unroll
        for (int k = 0; k < 8; k++) sv[k] = ssim[base + k];

        float x0v[16];
        #pragma unroll
        for (int o = 0; o < 16; o++) {
            float t = sb0[o];
            #pragma unroll
            for (int k = 0; k < 8; k++) t = fmaf(sw0[o*8 + k], sv[k], t);
            x0v[o] = fmaxf(t, 0.0f);
        }
        float x1v[8];
        #pragma unroll
        for (int j = 0; j < 8; j++) {
            float t = sb1[j];
            #pragma unroll
            for (int o = 0; o < 16; o++) t = fmaf(sw1[j*16 + o], x0v[o], t);
            x1v[j] = fmaxf(t, 0.0f);
        }
        float yv = sb2v[0];
        #pragma unroll
        for (int j = 0; j < 8; j++) yv = fmaf(sw2[j], x1v[j], yv);
        ssig[(s * 4 + d) * 32 + pp] = 1.0f / (1.0f + expf(-yv));
    }
    __syncthreads();

    // ---- depth max: vw[s][pix] = max_d sigmoid ----
    if (tid < 128) {
        const int s  = tid >> 5;
        const int pp = tid & 31;
        float m = ssig[(s * 4 + 0) * 32 + pp];
        #pragma unroll
        for (int d = 1; d < 4; d++) m = fmaxf(m, ssig[(s * 4 + d) * 32 + pp]);
        svw[s * 32 + pp] = m;
    }
    __syncthreads();

    // ---- accumulate + output (streaming stores) ----
    float simsum[D_] = {0.0f, 0.0f, 0.0f, 0.0f};
    float wsum = 0.0f;
    #pragma unroll
    for (int s = 0; s < 4; s++) {
        const float vw = svw[s * 32 + pixL];
        wsum += vw;
        #pragma unroll
        for (int d = 0; d < D_; d++)
            simsum[d] = fmaf(ssim[((s * 4 + d) * 32 + pixL) * 9 + g], vw, simsum[d]);
    }
    const float invw = 1.0f / wsum;
    #pragma unroll
    for (int d = 0; d < D_; d++)
        stg_cs(out + (size_t)(g * D_ + d) * HW_ + pix, simsum[d] * invw);
}

extern "C" void kernel_launch(void* const* d_in, const int* in_sizes, int n_in,
                              void* d_out, int out_size) {
    const float* features = (const float*)d_in[0];  // (5,1,32,384,384)
    const float* depths   = (const float*)d_in[1];  // (1,4,384,384)
    const float* Kall     = (const float*)d_in[2];  // (1,5,3,3)
    const float* Eall     = (const float*)d_in[3];  // (1,5,3,4)
    const float* w0 = (const float*)d_in[4];
    const float* b0 = (const float*)d_in[5];
    const float* w1 = (const float*)d_in[6];
    const float* b1 = (const float*)d_in[7];
    const float* w2 = (const float*)d_in[8];
    const float* b2 = (const float*)d_in[9];
    float* out = (float*)d_out;
    (void)in_sizes; (void)n_in; (void)out_size;

    dim3 tb(32, 32);
    transpose_setup_kernel<<<NPT * V_ + 1, tb>>>(features, Kall, Eall);

    gbinet_main_kernel<<<HW_ / 32, 256>>>(depths, w0, b0, w1, b1, w2, b2, out);
}

// round 14
// speedup vs baseline: 1.6871x; 1.0823x over previous
#include <cuda_runtime.h>
#include <cuda_bf16.h>
#include <math.h>

#define V_  5
#define C_  32
#define H_  384
#define W_  384
#define D_  4
#define G_  8
#define HW_ (H_ * W_)          // 147456
#define TPB_PIX 256            // pixels per transpose block
#define NPT (HW_ / TPB_PIX)    // transpose blocks per view: 576

// Transposed features (V, H*W, C): per-pixel channels contiguous, fp32.
__device__ float g_featT[(size_t)V_ * HW_ * C_];   // ~94.4 MB
// Folded projection per source view: uvd = M_s * (gx,gy,1) * dep + c_s
__device__ float g_M[4][9];
__device__ float g_c[4][3];

__device__ __forceinline__ void invert3f(const float* m, float* inv) {
    float a = m[0], b = m[1], c = m[2];
    float d = m[3], e = m[4], f = m[5];
    float g = m[6], h = m[7], i = m[8];
    float A  =  (e*i - f*h);
    float Bc = -(d*i - f*g);
    float Cc =  (d*h - e*g);
    float det = a*A + b*Bc + c*Cc;
    float id = 1.0f / det;
    inv[0] = A * id;
    inv[1] = -(b*i - c*h) * id;
    inv[2] =  (b*f - c*e) * id;
    inv[3] = Bc * id;
    inv[4] =  (a*i - c*g) * id;
    inv[5] = -(a*f - c*d) * id;
    inv[6] = Cc * id;
    inv[7] = -(a*h - b*g) * id;
    inv[8] =  (a*e - b*d) * id;
}

__device__ __forceinline__ void mat3mulf(const float* A, const float* B, float* Cm) {
    #pragma unroll
    for (int i = 0; i < 3; i++)
        #pragma unroll
        for (int j = 0; j < 3; j++)
            Cm[i*3+j] = A[i*3+0]*B[0*3+j] + A[i*3+1]*B[1*3+j] + A[i*3+2]*B[2*3+j];
}

// Fused: blocks [0, NPT*V) transpose CHW->HWC (256 pixels / 8 tiles per block);
// block NPT*V folds cameras (fp32, 4 threads).
__global__ void __launch_bounds__(1024)
transpose_setup_kernel(const float* __restrict__ f,
                       const float* __restrict__ K,
                       const float* __restrict__ E) {
    if (blockIdx.x == NPT * V_) {
        const int s = threadIdx.x + threadIdx.y * 32;
        if (s < 4) {
            float K0[9], Kinv[9], R0[9], Rinv[9], t0[3];
            #pragma unroll
            for (int i = 0; i < 9; i++) K0[i] = K[i];
            invert3f(K0, Kinv);
            #pragma unroll
            for (int i = 0; i < 3; i++) {
                #pragma unroll
                for (int j = 0; j < 3; j++) R0[i*3+j] = E[i*4+j];
                t0[i] = E[i*4+3];
            }
            invert3f(R0, Rinv);

            float Ks[9], Rs[9], ts[3];
            #pragma unroll
            for (int i = 0; i < 9; i++) Ks[i] = K[(s+1)*9 + i];
            #pragma unroll
            for (int i = 0; i < 3; i++) {
                #pragma unroll
                for (int j = 0; j < 3; j++) Rs[i*3+j] = E[(s+1)*12 + i*4 + j];
                ts[i] = E[(s+1)*12 + i*4 + 3];
            }
            float A[9], Bm[9], M[9];
            mat3mulf(Rs, Rinv, A);
            mat3mulf(Ks, A, Bm);
            mat3mulf(Bm, Kinv, M);
            #pragma unroll
            for (int i = 0; i < 3; i++) {
                float kt = Ks[i*3+0]*ts[0] + Ks[i*3+1]*ts[1] + Ks[i*3+2]*ts[2];
                float bt = Bm[i*3+0]*t0[0] + Bm[i*3+1]*t0[1] + Bm[i*3+2]*t0[2];
                g_c[s][i] = kt - bt;
            }
            #pragma unroll
            for (int i = 0; i < 9; i++) g_M[s][i] = M[i];
        }
        return;
    }
    __shared__ float sbuf[8][32][33];
    const int v  = blockIdx.x / NPT;
    const int p0 = (blockIdx.x - v * NPT) * TPB_PIX;
    const int tx = threadIdx.x, ty = threadIdx.y;
    #pragma unroll
    for (int t = 0; t < 8; t++)
        sbuf[t][ty][tx] = f[((size_t)v * C_ + ty) * HW_ + p0 + t * 32 + tx];
    __syncthreads();
    #pragma unroll
    for (int t = 0; t < 8; t++)
        g_featT[(size_t)v * HW_ * C_ + (size_t)(p0 + t * 32 + ty) * C_ + tx] =
            sbuf[t][tx][ty];
}

// Streaming store for output.
__device__ __forceinline__ void stg_cs(float* p, float v) {
    asm volatile("st.global.cs.f32 [%0], %1;" :: "l"(p), "f"(v) : "memory");
}
// Packed fp32x2 helpers (Blackwell dual-lane fp32)
__device__ __forceinline__ unsigned long long pack2(float lo, float hi) {
    unsigned long long r;
    asm("mov.b64 %0, {%1, %2};" : "=l"(r) : "f"(lo), "f"(hi));
    return r;
}
__device__ __forceinline__ float2 unpack2(unsigned long long v) {
    float lo, hi;
    asm("mov.b64 {%0, %1}, %2;" : "=f"(lo), "=f"(hi) : "l"(v));
    return make_float2(lo, hi);
}
__device__ __forceinline__ unsigned long long fma2(unsigned long long a,
                                                   unsigned long long b,
                                                   unsigned long long c) {
    unsigned long long r;
    asm("fma.rn.f32x2 %0, %1, %2, %3;" : "=l"(r) : "l"(a), "l"(b), "l"(c));
    return r;
}
__device__ __forceinline__ unsigned long long relu2(unsigned long long v) {
    float2 f = unpack2(v);
    return pack2(fmaxf(f.x, 0.0f), fmaxf(f.y, 0.0f));
}

// Main kernel: 256 threads = 32 pixels x 8 group-lanes. 2 blocks/SM (128 regs),
// gathers batched 2 views (32 loads) at a time; packed f32x2 MLP (2 items/lane).
__global__ void __launch_bounds__(256, 2)
gbinet_main_kernel(const float* __restrict__ depths,
                   const float* __restrict__ w0, const float* __restrict__ b0,
                   const float* __restrict__ w1, const float* __restrict__ b1,
                   const float* __restrict__ w2, const float* __restrict__ b2,
                   float* __restrict__ out) {
    __shared__ unsigned long long sw0d[128], sw1d[128];  // (w,w) duplicated
    __shared__ unsigned long long sb0d[16], sb1d[8], sw2d[8], sb2d[1];
    __shared__ float sM[4][9], sc[4][3];
    __shared__ float ssim[4 * 4 * 32 * 9];   // [s][d][pixL][g(pad 9)] = 18 KB
    __shared__ float ssig[4 * 4 * 32];       // [s][d][pixL]
    __shared__ float svw[4 * 32];            // [s][pixL]

    const int tid  = threadIdx.x;
    const int pixL = tid >> 3;
    const int g    = tid & 7;

    if (tid < 128) { float v = w0[tid];       sw0d[tid]       = pack2(v, v); }
    else           { float v = w1[tid - 128]; sw1d[tid - 128] = pack2(v, v); }
    if (tid < 16)               { float v = b0[tid];      sb0d[tid]      = pack2(v, v); }
    if (tid >= 16 && tid < 24)  { float v = b1[tid - 16]; sb1d[tid - 16] = pack2(v, v); }
    if (tid >= 24 && tid < 32)  { float v = w2[tid - 24]; sw2d[tid - 24] = pack2(v, v); }
    if (tid == 32)              { float v = b2[0];        sb2d[0]        = pack2(v, v); }
    if (tid >= 64 && tid < 64 + 36) {
        int i = tid - 64; sM[i / 9][i % 9] = g_M[i / 9][i % 9];
    }
    if (tid >= 100 && tid < 112) {
        int i = tid - 100; sc[i / 3][i % 3] = g_c[i / 3][i % 3];
    }

    const int pix = blockIdx.x * 32 + pixL;
    const int y = pix / W_;
    const int x = pix - y * W_;
    const float gx = (float)x + 0.5f;
    const float gy = (float)y + 0.5f;

    float dep[D_];
    #pragma unroll
    for (int d = 0; d < D_; d++) dep[d] = depths[d * HW_ + pix];

    const float4* __restrict__ fT4 = (const float4*)g_featT;
    const float4 ref = fT4[pix * 8 + g];

    __syncthreads();   // weights + M/c visible

    // ---- gather phase: 2 views (32 loads) batched per pass ----
    #pragma unroll 2
    for (int s = 0; s < 4; s++) {
        const float mx = sM[s][0]*gx + sM[s][1]*gy + sM[s][2];
        const float my = sM[s][3]*gx + sM[s][4]*gy + sM[s][5];
        const float mz = sM[s][6]*gx + sM[s][7]*gy + sM[s][8];
        const int vbase = (s + 1) * HW_;
        #pragma unroll
        for (int d = 0; d < D_; d++) {
            const float uh = fmaf(mx, dep[d], sc[s][0]);
            const float vh = fmaf(my, dep[d], sc[s][1]);
            const float zh = fmaf(mz, dep[d], sc[s][2]);
            const float rz = __fdividef(1.0f, zh + 1e-9f);
            const float px = uh * rz;
            const float py = vh * rz;

            const float x0f = floorf(px);
            const float y0f = floorf(py);
            const float wx1 = px - x0f, wx0v = 1.0f - wx1;
            const float wy1 = py - y0f, wy0v = 1.0f - wy1;

            float acc = 0.0f;
            #pragma unroll
            for (int corner = 0; corner < 4; corner++) {
                const float xf = x0f + (float)(corner & 1);
                const float yf = y0f + (float)(corner >> 1);
                const float w = ((corner & 1) ? wx1 : wx0v) *
                                ((corner >> 1) ? wy1 : wy0v);
                if (xf >= 0.0f && xf <= (float)(W_ - 1) &&
                    yf >= 0.0f && yf <= (float)(H_ - 1)) {
                    const int xi = (int)xf;
                    const int yi = (int)yf;
                    const int idx = (vbase + yi * W_ + xi) * 8 + g;
                    const float4 f = __ldg(fT4 + idx);
                    const float dot = f.x*ref.x + f.y*ref.y + f.z*ref.z + f.w*ref.w;
                    acc = fmaf(w, dot, acc);
                }
            }
            ssim[((s * 4 + d) * 32 + pixL) * 9 + g] = 0.25f * acc;
        }
    }
    __syncthreads();

    // ---- MLP phase: 512 items over 256 threads, 2 per thread PACKED f32x2 ----
    {
        const int i0 = tid, i1 = tid + 256;
        const int pp0 = i0 & 31, d0 = (i0 >> 5) & 3, s0 = i0 >> 7;
        const int pp1 = i1 & 31, d1 = (i1 >> 5) & 3, s1 = i1 >> 7;
        const int base0 = ((s0 * 4 + d0) * 32 + pp0) * 9;
        const int base1 = ((s1 * 4 + d1) * 32 + pp1) * 9;

        unsigned long long sv2[8];
        #pragma unroll
        for (int k = 0; k < 8; k++) sv2[k] = pack2(ssim[base0 + k], ssim[base1 + k]);

        unsigned long long x0v[16];
        #pragma unroll
        for (int o = 0; o < 16; o++) {
            unsigned long long t = sb0d[o];
            #pragma unroll
            for (int k = 0; k < 8; k++) t = fma2(sw0d[o*8 + k], sv2[k], t);
            x0v[o] = relu2(t);
        }
        unsigned long long x1v[8];
        #pragma unroll
        for (int j = 0; j < 8; j++) {
            unsigned long long t = sb1d[j];
            #pragma unroll
            for (int o = 0; o < 16; o++) t = fma2(sw1d[j*16 + o], x0v[o], t);
            x1v[j] = relu2(t);
        }
        unsigned long long yv = sb2d[0];
        #pragma unroll
        for (int j = 0; j < 8; j++) yv = fma2(sw2d[j], x1v[j], yv);
        const float2 yy = unpack2(yv);
        ssig[(s0 * 4 + d0) * 32 + pp0] = 1.0f / (1.0f + __expf(-yy.x));
        ssig[(s1 * 4 + d1) * 32 + pp1] = 1.0f / (1.0f + __expf(-yy.y));
    }
    __syncthreads();

    // ---- depth max: vw[s][pix] = max_d sigmoid ----
    if (tid < 128) {
        const int s  = tid >> 5;
        const int pp = tid & 31;
        float m = ssig[(s * 4 + 0) * 32 + pp];
        #pragma unroll
        for (int d = 1; d < 4; d++) m = fmaxf(m, ssig[(s * 4 + d) * 32 + pp]);
        svw[s * 32 + pp] = m;
    }
    __syncthreads();

    // ---- accumulate + output (streaming stores) ----
    float simsum[D_] = {0.0f, 0.0f, 0.0f, 0.0f};
    float wsum = 0.0f;
    #pragma unroll
    for (int s = 0; s < 4; s++) {
        const float vw = svw[s * 32 + pixL];
        wsum += vw;
        #pragma unroll
        for (int d = 0; d < D_; d++)
            simsum[d] = fmaf(ssim[((s * 4 + d) * 32 + pixL) * 9 + g], vw, simsum[d]);
    }
    const float invw = 1.0f / wsum;
    #pragma unroll
    for (int d = 0; d < D_; d++)
        stg_cs(out + (size_t)(g * D_ + d) * HW_ + pix, simsum[d] * invw);
}

extern "C" void kernel_launch(void* const* d_in, const int* in_sizes, int n_in,
                              void* d_out, int out_size) {
    const float* features = (const float*)d_in[0];  // (5,1,32,384,384)
    const float* depths   = (const float*)d_in[1];  // (1,4,384,384)
    const float* Kall     = (const float*)d_in[2];  // (1,5,3,3)
    const float* Eall     = (const float*)d_in[3];  // (1,5,3,4)
    const float* w0 = (const float*)d_in[4];
    const float* b0 = (const float*)d_in[5];
    const float* w1 = (const float*)d_in[6];
    const float* b1 = (const float*)d_in[7];
    const float* w2 = (const float*)d_in[8];
    const float* b2 = (const float*)d_in[9];
    float* out = (float*)d_out;
    (void)in_sizes; (void)n_in; (void)out_size;

    dim3 tb(32, 32);
    transpose_setup_kernel<<<NPT * V_ + 1, tb>>>(features, Kall, Eall);

    gbinet_main_kernel<<<HW_ / 32, 256>>>(depths, w0, b0, w1, b1, w2, b2, out);
}

// round 15
// speedup vs baseline: 2.4514x; 1.4530x over previous
#include <cuda_runtime.h>
#include <cuda_bf16.h>
#include <math.h>

#define V_  5
#define C_  32
#define H_  384
#define W_  384
#define D_  4
#define G_  8
#define HW_ (H_ * W_)          // 147456
#define TPB_PIX 256            // pixels per transpose block
#define NPT (HW_ / TPB_PIX)    // transpose blocks per view: 576

// Transposed features (V, H*W, C): per-pixel channels contiguous, fp32.
__device__ float g_featT[(size_t)V_ * HW_ * C_];   // ~94.4 MB
// Folded projection per source view: uvd = M_s * (gx,gy,1) * dep + c_s
__device__ float g_M[4][9];
__device__ float g_c[4][3];

__device__ __forceinline__ void invert3f(const float* m, float* inv) {
    float a = m[0], b = m[1], c = m[2];
    float d = m[3], e = m[4], f = m[5];
    float g = m[6], h = m[7], i = m[8];
    float A  =  (e*i - f*h);
    float Bc = -(d*i - f*g);
    float Cc =  (d*h - e*g);
    float det = a*A + b*Bc + c*Cc;
    float id = 1.0f / det;
    inv[0] = A * id;
    inv[1] = -(b*i - c*h) * id;
    inv[2] =  (b*f - c*e) * id;
    inv[3] = Bc * id;
    inv[4] =  (a*i - c*g) * id;
    inv[5] = -(a*f - c*d) * id;
    inv[6] = Cc * id;
    inv[7] = -(a*h - b*g) * id;
    inv[8] =  (a*e - b*d) * id;
}

__device__ __forceinline__ void mat3mulf(const float* A, const float* B, float* Cm) {
    #pragma unroll
    for (int i = 0; i < 3; i++)
        #pragma unroll
        for (int j = 0; j < 3; j++)
            Cm[i*3+j] = A[i*3+0]*B[0*3+j] + A[i*3+1]*B[1*3+j] + A[i*3+2]*B[2*3+j];
}

// Fused: blocks [0, NPT*V) transpose CHW->HWC (256 pixels / 8 tiles per block);
// block NPT*V folds cameras (fp32, 4 threads).
__global__ void __launch_bounds__(1024)
transpose_setup_kernel(const float* __restrict__ f,
                       const float* __restrict__ K,
                       const float* __restrict__ E) {
    if (blockIdx.x == NPT * V_) {
        const int s = threadIdx.x + threadIdx.y * 32;
        if (s < 4) {
            float K0[9], Kinv[9], R0[9], Rinv[9], t0[3];
            #pragma unroll
            for (int i = 0; i < 9; i++) K0[i] = K[i];
            invert3f(K0, Kinv);
            #pragma unroll
            for (int i = 0; i < 3; i++) {
                #pragma unroll
                for (int j = 0; j < 3; j++) R0[i*3+j] = E[i*4+j];
                t0[i] = E[i*4+3];
            }
            invert3f(R0, Rinv);

            float Ks[9], Rs[9], ts[3];
            #pragma unroll
            for (int i = 0; i < 9; i++) Ks[i] = K[(s+1)*9 + i];
            #pragma unroll
            for (int i = 0; i < 3; i++) {
                #pragma unroll
                for (int j = 0; j < 3; j++) Rs[i*3+j] = E[(s+1)*12 + i*4 + j];
                ts[i] = E[(s+1)*12 + i*4 + 3];
            }
            float A[9], Bm[9], M[9];
            mat3mulf(Rs, Rinv, A);
            mat3mulf(Ks, A, Bm);
            mat3mulf(Bm, Kinv, M);
            #pragma unroll
            for (int i = 0; i < 3; i++) {
                float kt = Ks[i*3+0]*ts[0] + Ks[i*3+1]*ts[1] + Ks[i*3+2]*ts[2];
                float bt = Bm[i*3+0]*t0[0] + Bm[i*3+1]*t0[1] + Bm[i*3+2]*t0[2];
                g_c[s][i] = kt - bt;
            }
            #pragma unroll
            for (int i = 0; i < 9; i++) g_M[s][i] = M[i];
        }
        return;
    }
    __shared__ float sbuf[8][32][33];
    const int v  = blockIdx.x / NPT;
    const int p0 = (blockIdx.x - v * NPT) * TPB_PIX;
    const int tx = threadIdx.x, ty = threadIdx.y;
    #pragma unroll
    for (int t = 0; t < 8; t++)
        sbuf[t][ty][tx] = f[((size_t)v * C_ + ty) * HW_ + p0 + t * 32 + tx];
    __syncthreads();
    #pragma unroll
    for (int t = 0; t < 8; t++)
        g_featT[(size_t)v * HW_ * C_ + (size_t)(p0 + t * 32 + ty) * C_ + tx] =
            sbuf[t][tx][ty];
}

// Streaming store for output.
__device__ __forceinline__ void stg_cs(float* p, float v) {
    asm volatile("st.global.cs.f32 [%0], %1;" :: "l"(p), "f"(v) : "memory");
}
// Packed fp32x2 helpers (Blackwell dual-lane fp32)
__device__ __forceinline__ unsigned long long pack2(float lo, float hi) {
    unsigned long long r;
    asm("mov.b64 %0, {%1, %2};" : "=l"(r) : "f"(lo), "f"(hi));
    return r;
}
__device__ __forceinline__ float2 unpack2(unsigned long long v) {
    float lo, hi;
    asm("mov.b64 {%0, %1}, %2;" : "=f"(lo), "=f"(hi) : "l"(v));
    return make_float2(lo, hi);
}
__device__ __forceinline__ unsigned long long fma2(unsigned long long a,
                                                   unsigned long long b,
                                                   unsigned long long c) {
    unsigned long long r;
    asm("fma.rn.f32x2 %0, %1, %2, %3;" : "=l"(r) : "l"(a), "l"(b), "l"(c));
    return r;
}
__device__ __forceinline__ unsigned long long relu2(unsigned long long v) {
    float2 f = unpack2(v);
    return pack2(fmaxf(f.x, 0.0f), fmaxf(f.y, 0.0f));
}

// Main kernel: 256 threads = 32 pixels x 8 group-lanes. 2 blocks/SM (128 regs),
// gathers batched 2 views; packed f32x2 MLP with LDS.128-paired weights.
__global__ void __launch_bounds__(256, 2)
gbinet_main_kernel(const float* __restrict__ depths,
                   const float* __restrict__ w0, const float* __restrict__ b0,
                   const float* __restrict__ w1, const float* __restrict__ b1,
                   const float* __restrict__ w2, const float* __restrict__ b2,
                   float* __restrict__ out) {
    // weight pairs: .x = (w[2i],w[2i]), .y = (w[2i+1],w[2i+1]) -> one LDS.128
    __shared__ ulonglong2 sw0q[64], sw1q[64], sw2q[4];
    __shared__ unsigned long long sb0d[16], sb1d[8], sb2d[1];
    __shared__ float sM[4][9], sc[4][3];
    __shared__ float ssim[4 * 4 * 32 * 9];   // [s][d][pixL][g(pad 9)] = 18 KB
    __shared__ float ssig[4 * 4 * 32];       // [s][d][pixL]
    __shared__ float svw[4 * 32];            // [s][pixL]

    const int tid  = threadIdx.x;
    const int pixL = tid >> 3;
    const int g    = tid & 7;

    if (tid < 64) {
        float v0 = w0[2*tid], v1 = w0[2*tid + 1];
        sw0q[tid] = make_ulonglong2(pack2(v0, v0), pack2(v1, v1));
    } else if (tid < 128) {
        int i = tid - 64;
        float v0 = w1[2*i], v1 = w1[2*i + 1];
        sw1q[i] = make_ulonglong2(pack2(v0, v0), pack2(v1, v1));
    } else if (tid < 132) {
        int i = tid - 128;
        float v0 = w2[2*i], v1 = w2[2*i + 1];
        sw2q[i] = make_ulonglong2(pack2(v0, v0), pack2(v1, v1));
    } else if (tid < 148) {
        float v = b0[tid - 132]; sb0d[tid - 132] = pack2(v, v);
    } else if (tid < 156) {
        float v = b1[tid - 148]; sb1d[tid - 148] = pack2(v, v);
    } else if (tid == 156) {
        float v = b2[0]; sb2d[0] = pack2(v, v);
    }
    if (tid >= 160 && tid < 160 + 36) {
        int i = tid - 160; sM[i / 9][i % 9] = g_M[i / 9][i % 9];
    }
    if (tid >= 196 && tid < 208) {
        int i = tid - 196; sc[i / 3][i % 3] = g_c[i / 3][i % 3];
    }

    const int pix = blockIdx.x * 32 + pixL;
    const int y = pix / W_;
    const int x = pix - y * W_;
    const float gx = (float)x + 0.5f;
    const float gy = (float)y + 0.5f;

    float dep[D_];
    #pragma unroll
    for (int d = 0; d < D_; d++) dep[d] = depths[d * HW_ + pix];

    const float4* __restrict__ fT4 = (const float4*)g_featT;
    const float4 ref = fT4[pix * 8 + g];

    __syncthreads();   // weights + M/c visible

    // ---- gather phase: 2 views (32 loads) batched per pass ----
    #pragma unroll 2
    for (int s = 0; s < 4; s++) {
        const float mx = sM[s][0]*gx + sM[s][1]*gy + sM[s][2];
        const float my = sM[s][3]*gx + sM[s][4]*gy + sM[s][5];
        const float mz = sM[s][6]*gx + sM[s][7]*gy + sM[s][8];
        const int vbase = (s + 1) * HW_;
        #pragma unroll
        for (int d = 0; d < D_; d++) {
            const float uh = fmaf(mx, dep[d], sc[s][0]);
            const float vh = fmaf(my, dep[d], sc[s][1]);
            const float zh = fmaf(mz, dep[d], sc[s][2]);
            const float rz = __fdividef(1.0f, zh + 1e-9f);
            const float px = uh * rz;
            const float py = vh * rz;

            const float x0f = floorf(px);
            const float y0f = floorf(py);
            const float wx1 = px - x0f, wx0v = 1.0f - wx1;
            const float wy1 = py - y0f, wy0v = 1.0f - wy1;

            float acc = 0.0f;
            #pragma unroll
            for (int corner = 0; corner < 4; corner++) {
                const float xf = x0f + (float)(corner & 1);
                const float yf = y0f + (float)(corner >> 1);
                const float w = ((corner & 1) ? wx1 : wx0v) *
                                ((corner >> 1) ? wy1 : wy0v);
                if (xf >= 0.0f && xf <= (float)(W_ - 1) &&
                    yf >= 0.0f && yf <= (float)(H_ - 1)) {
                    const int xi = (int)xf;
                    const int yi = (int)yf;
                    const int idx = (vbase + yi * W_ + xi) * 8 + g;
                    const float4 f = __ldg(fT4 + idx);
                    const float dot = f.x*ref.x + f.y*ref.y + f.z*ref.z + f.w*ref.w;
                    acc = fmaf(w, dot, acc);
                }
            }
            ssim[((s * 4 + d) * 32 + pixL) * 9 + g] = 0.25f * acc;
        }
    }
    __syncthreads();

    // ---- MLP phase: 512 items over 256 threads, 2 per thread PACKED f32x2 ----
    {
        const int i0 = tid, i1 = tid + 256;
        const int pp0 = i0 & 31, d0 = (i0 >> 5) & 3, s0 = i0 >> 7;
        const int pp1 = i1 & 31, d1 = (i1 >> 5) & 3, s1 = i1 >> 7;
        const int base0 = ((s0 * 4 + d0) * 32 + pp0) * 9;
        const int base1 = ((s1 * 4 + d1) * 32 + pp1) * 9;

        unsigned long long sv2[8];
        #pragma unroll
        for (int k = 0; k < 8; k++) sv2[k] = pack2(ssim[base0 + k], ssim[base1 + k]);

        unsigned long long x0v[16];
        #pragma unroll
        for (int o = 0; o < 16; o++) {
            unsigned long long t = sb0d[o];
            #pragma unroll
            for (int k2 = 0; k2 < 4; k2++) {
                const ulonglong2 w = sw0q[o*4 + k2];
                t = fma2(w.x, sv2[2*k2],     t);
                t = fma2(w.y, sv2[2*k2 + 1], t);
            }
            x0v[o] = relu2(t);
        }
        unsigned long long x1v[8];
        #pragma unroll
        for (int j = 0; j < 8; j++) {
            unsigned long long t = sb1d[j];
            #pragma unroll
            for (int o2 = 0; o2 < 8; o2++) {
                const ulonglong2 w = sw1q[j*8 + o2];
                t = fma2(w.x, x0v[2*o2],     t);
                t = fma2(w.y, x0v[2*o2 + 1], t);
            }
            x1v[j] = relu2(t);
        }
        unsigned long long yv = sb2d[0];
        #pragma unroll
        for (int j2 = 0; j2 < 4; j2++) {
            const ulonglong2 w = sw2q[j2];
            yv = fma2(w.x, x1v[2*j2],     yv);
            yv = fma2(w.y, x1v[2*j2 + 1], yv);
        }
        const float2 yy = unpack2(yv);
        ssig[(s0 * 4 + d0) * 32 + pp0] = 1.0f / (1.0f + __expf(-yy.x));
        ssig[(s1 * 4 + d1) * 32 + pp1] = 1.0f / (1.0f + __expf(-yy.y));
    }
    __syncthreads();

    // ---- depth max: vw[s][pix] = max_d sigmoid ----
    if (tid < 128) {
        const int s  = tid >> 5;
        const int pp = tid & 31;
        float m = ssig[(s * 4 + 0) * 32 + pp];
        #pragma unroll
        for (int d = 1; d < 4; d++) m = fmaxf(m, ssig[(s * 4 + d) * 32 + pp]);
        svw[s * 32 + pp] = m;
    }
    __syncthreads();

    // ---- accumulate + output (streaming stores) ----
    float simsum[D_] = {0.0f, 0.0f, 0.0f, 0.0f};
    float wsum = 0.0f;
    #pragma unroll
    for (int s = 0; s < 4; s++) {
        const float vw = svw[s * 32 + pixL];
        wsum += vw;
        #pragma unroll
        for (int d = 0; d < D_; d++)
            simsum[d] = fmaf(ssim[((s * 4 + d) * 32 + pixL) * 9 + g], vw, simsum[d]);
    }
    const float invw = 1.0f / wsum;
    #pragma unroll
    for (int d = 0; d < D_; d++)
        stg_cs(out + (size_t)(g * D_ + d) * HW_ + pix, simsum[d] * invw);
}

extern "C" void kernel_launch(void* const* d_in, const int* in_sizes, int n_in,
                              void* d_out, int out_size) {
    const float* features = (const float*)d_in[0];  // (5,1,32,384,384)
    const float* depths   = (const float*)d_in[1];  // (1,4,384,384)
    const float* Kall     = (const float*)d_in[2];  // (1,5,3,3)
    const float* Eall     = (const float*)d_in[3];  // (1,5,3,4)
    const float* w0 = (const float*)d_in[4];
    const float* b0 = (const float*)d_in[5];
    const float* w1 = (const float*)d_in[6];
    const float* b1 = (const float*)d_in[7];
    const float* w2 = (const float*)d_in[8];
    const float* b2 = (const float*)d_in[9];
    float* out = (float*)d_out;
    (void)in_sizes; (void)n_in; (void)out_size;

    dim3 tb(32, 32);
    transpose_setup_kernel<<<NPT * V_ + 1, tb>>>(features, Kall, Eall);

    gbinet_main_kernel<<<HW_ / 32, 256>>>(depths, w0, b0, w1, b1, w2, b2, out);
}